// round 7
// baseline (speedup 1.0000x reference)
#include <cuda_runtime.h>
#include <math.h>

#define BB 8
#define NN 8192
#define SS 2048
#define KK 32
#define CNT (BB*SS*KK)          // 524288 elements per layer
#define OUT_XYZ_ELEMS (BB*SS*3) // 49152

typedef unsigned long long ull;

// ---------------- scratch (static device memory; no runtime allocation) ----
__device__ float g_bufA[(size_t)CNT * 32];  // 64 MB : z1 (32ch), channel-major [c][e]
__device__ float g_bufB[(size_t)CNT * 32];  // 64 MB : z2 (32ch), channel-major
__device__ float g_max[(size_t)BB * SS * 64]; // 4 MB : per-(b,s) max_k z3, [bs][o]
__device__ int   g_fps[BB * SS];
__device__ int   g_ball[BB * SS * KK];
__device__ float g_stats[3 * 128];          // per layer: [0..63]=sum, [64..127]=sumsq
__device__ float g_sink;                    // DCE-blocker for L1 warm loop

// ---------------- packed f32x2 helpers (sm_103a) ---------------------------
__device__ __forceinline__ ull pack2(float lo, float hi) {
    ull r; asm("mov.b64 %0,{%1,%2};" : "=l"(r) : "f"(lo), "f"(hi)); return r;
}
__device__ __forceinline__ void unpack2(ull v, float& lo, float& hi) {
    asm("mov.b64 {%0,%1},%2;" : "=f"(lo), "=f"(hi) : "l"(v));
}
__device__ __forceinline__ ull add2(ull a, ull b) {
    ull r; asm("add.rn.f32x2 %0,%1,%2;" : "=l"(r) : "l"(a), "l"(b)); return r;
}
__device__ __forceinline__ ull mul2(ull a, ull b) {
    ull r; asm("mul.rn.f32x2 %0,%1,%2;" : "=l"(r) : "l"(a), "l"(b)); return r;
}
__device__ __forceinline__ ull fma2(ull a, ull b, ull c) {
    ull r; asm("fma.rn.f32x2 %0,%1,%2,%3;" : "=l"(r) : "l"(a), "l"(b), "l"(c)); return r;
}

__device__ __forceinline__ unsigned smem_u32(const void* p) {
    unsigned a;
    asm("{ .reg .u64 t; cvta.to.shared.u64 t, %1; cvt.u32.u64 %0, t; }"
        : "=r"(a) : "l"(p));
    return a;
}

// ============================================================================
// 1) Farthest point sampling, 2-CTA cluster per batch (grid = 16).
//    Each CTA: 512 threads x 8 points (4 packed pairs) in registers, distance
//    in the validated bit-exact (p-c)^2 packed form. Per iteration:
//    update + fmax tree, REDUX warp max, rescan tie-break, REDUX min idx,
//    shared atomicMax, 1 barrier, then ONE remote st.shared::cluster of the
//    64-bit key into the peer + mbarrier arrive (release.cluster). Waiters use
//    try_wait.parity acquire.cluster; winner = max(own key, peer key) exactly.
// ============================================================================
__global__ void __launch_bounds__(512) __cluster_dims__(2, 1, 1)
fps_kernel(const float* __restrict__ xyz)
{
    const int b    = blockIdx.x >> 1;          // batch
    const int rank = blockIdx.x & 1;           // rank within cluster
    const int peer = rank ^ 1;
    const float* base = xyz + (size_t)b * NN * 3;
    const int t = threadIdx.x;
    const int lane = t & 31;
    const int off = rank * 4096;               // this CTA's point range

    __shared__ ull sbest[3];
    __shared__ ull inbox[2];
    __shared__ ull mbar;

    const unsigned inbox_a = smem_u32(&inbox[0]);
    const unsigned mbar_a  = smem_u32(&mbar);

    if (t == 0) {
        sbest[0] = 0ull; sbest[1] = 0ull; sbest[2] = 0ull;
        asm volatile("mbarrier.init.shared.b64 [%0], 1;" :: "r"(mbar_a) : "memory");
    }
    __syncthreads();
    // cluster barrier: peer's mbarrier must be initialized before any arrive
    asm volatile("barrier.cluster.arrive.aligned;" ::: "memory");
    asm volatile("barrier.cluster.wait.aligned;"   ::: "memory");

    // 8 points per thread: dd[j] <-> global point index off + t + j*512
    ull px[4], py[4], pz[4];
    float dd[8];
#pragma unroll
    for (int k = 0; k < 4; k++) {
        const int p0 = off + t + (2 * k) * 512;
        const int p1 = off + t + (2 * k + 1) * 512;
        px[k] = pack2(base[3 * p0 + 0], base[3 * p1 + 0]);
        py[k] = pack2(base[3 * p0 + 1], base[3 * p1 + 1]);
        pz[k] = pack2(base[3 * p0 + 2], base[3 * p1 + 2]);
    }
#pragma unroll
    for (int j = 0; j < 8; j++) dd[j] = 1e10f;

    // Warm L1 with the FULL batch (winner coords may live in the peer half).
    // (After the cluster sync above, which flushes L1.)
    {
        float s = 0.f;
        for (int i = t; i < NN * 3; i += 512) s += base[i];
        if (__float_as_uint(s) == 0x7f800001u) g_sink = s;  // unreachable; keeps loads
    }

    float cx = base[0], cy = base[1], cz = base[2];
    int cur = 0;
    int slot = 0, nslot = 1, rslot = 2;

    for (int it = 0; it < SS; it++) {
        if (t == 0) {
            if (rank == 0) g_fps[b * SS + it] = cur;
            sbest[nslot] = 0ull;               // reset next slot (barrier-ordered)
        }
        const ull ncx = pack2(-cx, -cx);
        const ull ncy = pack2(-cy, -cy);
        const ull ncz = pack2(-cz, -cz);

        float m = 0.f;
#pragma unroll
        for (int k = 0; k < 4; k++) {
            ull dx = add2(px[k], ncx);
            ull dy = add2(py[k], ncy);
            ull dz = add2(pz[k], ncz);
            ull d2 = mul2(dx, dx);
            d2 = fma2(dy, dy, d2);
            d2 = fma2(dz, dz, d2);
            float dlo, dhi; unpack2(d2, dlo, dhi);
            const float nlo = fminf(dd[2 * k],     dlo);
            const float nhi = fminf(dd[2 * k + 1], dhi);
            dd[2 * k]     = nlo;
            dd[2 * k + 1] = nhi;
            m = fmaxf(m, fmaxf(nlo, nhi));
        }
        const unsigned mb   = __float_as_uint(m);
        const unsigned wmax = __reduce_max_sync(0xffffffffu, mb);
        unsigned bi = 0xffffffffu;
        if (mb == wmax) {
#pragma unroll
            for (int j = 7; j >= 0; j--)
                if (__float_as_uint(dd[j]) == wmax) bi = (unsigned)(off + t + j * 512);
        }
        const unsigned rid = __reduce_min_sync(0xffffffffu, bi);
        if (lane == 0)
            atomicMax(&sbest[slot],
                      ((ull)wmax << 32) | (ull)(unsigned)(NN - 1 - (int)rid));
        __syncthreads();

        // exchange bests: one remote 64-bit store + arrive into the peer CTA
        if (t == 0) {
            const ull mykey = sbest[slot];
            asm volatile(
                "{\n\t"
                ".reg .b32 ra, rb;\n\t"
                "mapa.shared::cluster.u32 ra, %0, %1;\n\t"
                "st.shared::cluster.b64 [ra], %2;\n\t"
                "mapa.shared::cluster.u32 rb, %3, %1;\n\t"
                "mbarrier.arrive.release.cluster.shared::cluster.b64 _, [rb];\n\t"
                "}"
                :: "r"(inbox_a + ((unsigned)(it & 1) << 3)), "r"(peer),
                   "l"(mykey), "r"(mbar_a)
                : "memory");
        }
        // wait for the peer's arrival (parity = it&1)
        {
            const unsigned par = (unsigned)(it & 1);
            unsigned done;
            do {
                asm volatile(
                    "{\n\t"
                    ".reg .pred p;\n\t"
                    "mbarrier.try_wait.parity.acquire.cluster.shared::cta.b64 p, [%1], %2;\n\t"
                    "selp.b32 %0, 1, 0, p;\n\t"
                    "}"
                    : "=r"(done) : "r"(mbar_a), "r"(par) : "memory");
            } while (!done);
        }

        const ull ok = sbest[slot];
        const ull pk = inbox[it & 1];
        const ull win = ok > pk ? ok : pk;
        cur = NN - 1 - (int)(unsigned)(win & 0xffffffffu);
        cx = base[3 * cur + 0];   // L1 hit (warmed)
        cy = base[3 * cur + 1];
        cz = base[3 * cur + 2];

        const int tmp = slot; slot = nslot; nslot = rslot; rslot = tmp;
    }

    // no CTA may exit while the peer could still target its SMEM
    asm volatile("barrier.cluster.arrive.aligned;" ::: "memory");
    asm volatile("barrier.cluster.wait.aligned;"   ::: "memory");
}

// ============================================================================
// 2) new_xyz gather + ball query, smem-tiled. Block = 8 warps = 8 centroids,
//    all in the same batch. Block 0 also zeroes g_stats (all 384, strided).
// ============================================================================
#define TPTS 1024
__global__ void __launch_bounds__(256) bq_kernel(const float* __restrict__ xyz,
                                                 float* __restrict__ newxyz)
{
    const int tid = threadIdx.x;
    if (blockIdx.x == 0) {
        for (int i = tid; i < 384; i += 256) g_stats[i] = 0.f;
    }

    const int warp = tid >> 5, lane = tid & 31;
    const int gs = blockIdx.x * 8 + warp;          // 0 .. 16383
    const int b  = gs >> 11;                        // same for whole block
    const float* base = xyz + (size_t)b * NN * 3;

    __shared__ float spts[TPTS * 3];
    __shared__ int   sidx[8][KK];
    __shared__ int   sdone;
    if (tid == 0) sdone = 0;

    const int ci = g_fps[gs];
    const float cx = base[3 * ci + 0];
    const float cy = base[3 * ci + 1];
    const float cz = base[3 * ci + 2];
    if (lane < 3) newxyz[(size_t)gs * 3 + lane] = base[3 * ci + lane];

    const float r2 = (float)(0.2 * 0.2);
    int cnt = 0, first = 0x7fffffff;
    bool done = false;

    for (int tile = 0; tile < NN; tile += TPTS) {
        __syncthreads();
        if (sdone == 8) break;
        for (int i = tid; i < TPTS * 3; i += 256)
            spts[i] = base[(size_t)tile * 3 + i];
        __syncthreads();

        if (!done) {
            for (int p0 = 0; p0 < TPTS; p0 += 32) {
                const int p = p0 + lane;
                float dx = spts[3 * p + 0] - cx;
                float dy = spts[3 * p + 1] - cy;
                float dz = spts[3 * p + 2] - cz;
                float sq = dx * dx + dy * dy + dz * dz;
                bool  in = !(sq > r2);
                unsigned mm = __ballot_sync(0xffffffffu, in);
                if (in) {
                    int pos = cnt + __popc(mm & ((1u << lane) - 1u));
                    if (pos < KK) sidx[warp][pos] = tile + p;
                    if (pos == 0) first = tile + p;
                }
                cnt += __popc(mm);
                if (cnt >= KK) break;
            }
            if (cnt >= KK) {
                done = true;
                if (lane == 0) atomicAdd(&sdone, 1);
            }
        }
    }
#pragma unroll
    for (int off = 16; off > 0; off >>= 1)
        first = min(first, __shfl_down_sync(0xffffffffu, first, off));
    first = __shfl_sync(0xffffffffu, first, 0);

    const int cc = cnt < KK ? cnt : KK;
    const int v  = (lane < cc) ? sidx[warp][lane] : first;
    g_ball[(size_t)gs * KK + lane] = v;
}

// ============================================================================
// stats: warp reduce (sum, sumsq) then shared atomics
// ============================================================================
__device__ __forceinline__ void warp_stat_accum2(float v, float v2, int c, int lane,
                                                 float* ssum, float* ssq)
{
#pragma unroll
    for (int off = 16; off > 0; off >>= 1) {
        v  += __shfl_down_sync(0xffffffffu, v,  off);
        v2 += __shfl_down_sync(0xffffffffu, v2, off);
    }
    if (lane == 0) { atomicAdd(&ssum[c], v); atomicAdd(&ssq[c], v2); }
}

// BN affine from stats (same math as the old fin_kernel, computed inline)
__device__ __forceinline__ void bn_affine(int L, int c,
                                          const float* __restrict__ g,
                                          const float* __restrict__ be,
                                          float& a, float& cc)
{
    const float inv  = 1.f / (float)CNT;
    const float mean = g_stats[L * 128 + c] * inv;
    const float var  = g_stats[L * 128 + 64 + c] * inv - mean * mean;
    a  = g[c] * rsqrtf(var + 1e-5f);
    cc = be[c] - mean * a;
}

// ============================================================================
// 3) Layer 1: gather features (2 elements/thread), packed 6->32 conv, z1, stats.
// ============================================================================
__global__ void __launch_bounds__(256) l1_kernel(const float* __restrict__ xyz,
                                                 const float* __restrict__ pts,
                                                 const float* __restrict__ w,
                                                 const float* __restrict__ bias,
                                                 const float* __restrict__ newxyz)
{
    __shared__ ull   swd[192];
    __shared__ ull   sb2[32];
    __shared__ float ssum[32], ssq[32];
    const int tid = threadIdx.x, lane = tid & 31;
    if (tid < 192) { float v = w[tid]; swd[tid] = pack2(v, v); }
    if (tid < 32)  { float v = bias[tid]; sb2[tid] = pack2(v, v); ssum[tid] = 0.f; ssq[tid] = 0.f; }
    __syncthreads();

    const int gt = blockIdx.x * 256 + tid;        // pair id < CNT/2
    const int e0 = 2 * gt;
    const int bs = e0 >> 5;
    const int b  = bs >> 11;
    const int2 pp = *(const int2*)&g_ball[e0];
    const float* xb = xyz + (size_t)b * NN * 3;
    const float* pb = pts + (size_t)b * NN * 3;
    const float nx = newxyz[(size_t)bs * 3 + 0];
    const float ny = newxyz[(size_t)bs * 3 + 1];
    const float nz = newxyz[(size_t)bs * 3 + 2];

    ull in2[6];
    in2[0] = pack2(xb[3 * pp.x + 0] - nx, xb[3 * pp.y + 0] - nx);
    in2[1] = pack2(xb[3 * pp.x + 1] - ny, xb[3 * pp.y + 1] - ny);
    in2[2] = pack2(xb[3 * pp.x + 2] - nz, xb[3 * pp.y + 2] - nz);
    in2[3] = pack2(pb[3 * pp.x + 0], pb[3 * pp.y + 0]);
    in2[4] = pack2(pb[3 * pp.x + 1], pb[3 * pp.y + 1]);
    in2[5] = pack2(pb[3 * pp.x + 2], pb[3 * pp.y + 2]);

#pragma unroll 4
    for (int o = 0; o < 32; o++) {
        ull acc = sb2[o];
#pragma unroll
        for (int i = 0; i < 6; i++) acc = fma2(swd[o * 6 + i], in2[i], acc);
        *(ull*)&g_bufA[(size_t)o * CNT + e0] = acc;     // STG.64, coalesced
        float lo, hi; unpack2(acc, lo, hi);
        warp_stat_accum2(lo + hi, fmaf(hi, hi, lo * lo), o, lane, ssum, ssq);
    }
    __syncthreads();
    if (tid < 32) {
        atomicAdd(&g_stats[0 * 128 + tid],      ssum[tid]);
        atomicAdd(&g_stats[0 * 128 + 64 + tid], ssq[tid]);
    }
}

// ============================================================================
// 4) Layer 2: BN1+relu on z1 (affine computed inline from stats), packed
//    32->32 conv (2 elements/thread), z2, stats.
// ============================================================================
__global__ void __launch_bounds__(256) l2_kernel(const float* __restrict__ w,
                                                 const float* __restrict__ bias,
                                                 const float* __restrict__ g0,
                                                 const float* __restrict__ be0)
{
    __shared__ ull   swd[1024];
    __shared__ ull   sb2[32], sa2[32], sc2[32];
    __shared__ float ssum[32], ssq[32];
    const int tid = threadIdx.x, lane = tid & 31;
    for (int i = tid; i < 1024; i += 256) { float v = w[i]; swd[i] = pack2(v, v); }
    if (tid < 32) {
        float v = bias[tid]; sb2[tid] = pack2(v, v);
        float a, c; bn_affine(0, tid, g0, be0, a, c);
        sa2[tid] = pack2(a, a); sc2[tid] = pack2(c, c);
        ssum[tid] = 0.f; ssq[tid] = 0.f;
    }
    __syncthreads();

    const int e0 = 2 * (blockIdx.x * 256 + tid);
    ull h2[32];
#pragma unroll
    for (int i = 0; i < 32; i++) {
        ull z = *(const ull*)&g_bufA[(size_t)i * CNT + e0];
        ull t = fma2(sa2[i], z, sc2[i]);
        float lo, hi; unpack2(t, lo, hi);
        h2[i] = pack2(fmaxf(lo, 0.f), fmaxf(hi, 0.f));
    }
#pragma unroll 2
    for (int o = 0; o < 32; o++) {
        ull acc = sb2[o];
#pragma unroll
        for (int i = 0; i < 32; i++) acc = fma2(swd[o * 32 + i], h2[i], acc);
        *(ull*)&g_bufB[(size_t)o * CNT + e0] = acc;
        float lo, hi; unpack2(acc, lo, hi);
        warp_stat_accum2(lo + hi, fmaf(hi, hi, lo * lo), o, lane, ssum, ssq);
    }
    __syncthreads();
    if (tid < 32) {
        atomicAdd(&g_stats[1 * 128 + tid],      ssum[tid]);
        atomicAdd(&g_stats[1 * 128 + 64 + tid], ssq[tid]);
    }
}

// ============================================================================
// 5) Layer 3: BN2+relu on z2 (affine inline), packed 32->64 conv, stats, and
//    FUSED max over k: z3 never hits DRAM (bit-exact: a3>0, monotone fmaf/relu).
// ============================================================================
__global__ void __launch_bounds__(256) l3_kernel(const float* __restrict__ w,
                                                 const float* __restrict__ bias,
                                                 const float* __restrict__ g1,
                                                 const float* __restrict__ be1)
{
    __shared__ ull   swd[2048];       // 16KB
    __shared__ ull   sb2[64], sa2[32], sc2[32];
    __shared__ float ssum[64], ssq[64];
    __shared__ float smax[16][64];    // 16 bs-groups per block
    const int tid = threadIdx.x, lane = tid & 31, warp = tid >> 5;
    for (int i = tid; i < 2048; i += 256) { float v = w[i]; swd[i] = pack2(v, v); }
    if (tid < 64) { float v = bias[tid]; sb2[tid] = pack2(v, v); ssum[tid] = 0.f; ssq[tid] = 0.f; }
    if (tid < 32) {
        float a, c; bn_affine(1, tid, g1, be1, a, c);
        sa2[tid] = pack2(a, a); sc2[tid] = pack2(c, c);
    }
    __syncthreads();

    const int e0 = 2 * (blockIdx.x * 256 + tid);
    ull h2[32];
#pragma unroll
    for (int i = 0; i < 32; i++) {
        ull z = *(const ull*)&g_bufB[(size_t)i * CNT + e0];
        ull t = fma2(sa2[i], z, sc2[i]);
        float lo, hi; unpack2(t, lo, hi);
        h2[i] = pack2(fmaxf(lo, 0.f), fmaxf(hi, 0.f));
    }
    const int seg = (warp << 1) + (lane >> 4);    // bs-group within block (0..15)
#pragma unroll 1
    for (int o = 0; o < 64; o++) {
        ull acc = sb2[o];
#pragma unroll
        for (int i = 0; i < 32; i++) acc = fma2(swd[o * 32 + i], h2[i], acc);
        float lo, hi; unpack2(acc, lo, hi);
        float mx = fmaxf(lo, hi);
#pragma unroll
        for (int off = 8; off > 0; off >>= 1)
            mx = fmaxf(mx, __shfl_down_sync(0xffffffffu, mx, off, 16));
        if ((lane & 15) == 0) smax[seg][o] = mx;
        warp_stat_accum2(lo + hi, fmaf(hi, hi, lo * lo), o, lane, ssum, ssq);
    }
    __syncthreads();
    {
        const int bs0 = blockIdx.x * 16;
        for (int i = tid; i < 16 * 64; i += 256)
            g_max[(size_t)bs0 * 64 + i] = smax[i >> 6][i & 63];
    }
    if (tid < 64) {
        atomicAdd(&g_stats[2 * 128 + tid],      ssum[tid]);
        atomicAdd(&g_stats[2 * 128 + 64 + tid], ssq[tid]);
    }
}

// ============================================================================
// 6) Finalize: BN3 affine (inline from stats) + relu on the per-(bs,o) maxima.
// ============================================================================
__global__ void __launch_bounds__(256) final_kernel(const float* __restrict__ g2,
                                                    const float* __restrict__ be2,
                                                    float* __restrict__ out)
{
    __shared__ float sa[64], sc[64];
    const int tid = threadIdx.x;
    if (tid < 64) {
        float a, c; bn_affine(2, tid, g2, be2, a, c);
        sa[tid] = a; sc[tid] = c;
    }
    __syncthreads();

    const int idx = blockIdx.x * 256 + tid;       // < BB*SS*64
    const int o = idx & 63;
    const float v = g_max[idx];
    out[OUT_XYZ_ELEMS + idx] = fmaxf(fmaf(sa[o], v, sc[o]), 0.f);
}

// ============================================================================
extern "C" void kernel_launch(void* const* d_in, const int* in_sizes, int n_in,
                              void* d_out, int out_size)
{
    const float* xyz = (const float*)d_in[0];
    const float* pts = (const float*)d_in[1];
    const float* w0  = (const float*)d_in[2];
    const float* b0  = (const float*)d_in[3];
    const float* g0  = (const float*)d_in[4];
    const float* be0 = (const float*)d_in[5];
    const float* w1  = (const float*)d_in[6];
    const float* b1  = (const float*)d_in[7];
    const float* g1  = (const float*)d_in[8];
    const float* be1 = (const float*)d_in[9];
    const float* w2  = (const float*)d_in[10];
    const float* b2  = (const float*)d_in[11];
    const float* g2  = (const float*)d_in[12];
    const float* be2 = (const float*)d_in[13];
    float* out = (float*)d_out;

    fps_kernel<<<BB * 2, 512>>>(xyz);
    bq_kernel<<<(BB * SS) / 8, 256>>>(xyz, out);
    l1_kernel<<<CNT / 512, 256>>>(xyz, pts, w0, b0, out);
    l2_kernel<<<CNT / 512, 256>>>(w1, b1, g0, be0);
    l3_kernel<<<CNT / 512, 256>>>(w2, b2, g1, be1);
    final_kernel<<<(BB * SS * 64) / 256, 256>>>(g2, be2, out);
}

// round 8
// speedup vs baseline: 1.5931x; 1.5931x over previous
#include <cuda_runtime.h>
#include <math.h>

#define BB 8
#define NN 8192
#define SS 2048
#define KK 32
#define CNT (BB*SS*KK)          // 524288 elements per layer
#define OUT_XYZ_ELEMS (BB*SS*3) // 49152

typedef unsigned long long ull;

// ---------------- scratch (static device memory; no runtime allocation) ----
__device__ float g_bufA[(size_t)CNT * 32];  // 64 MB : z1 (32ch), channel-major [c][e]
__device__ float g_bufB[(size_t)CNT * 32];  // 64 MB : z2 (32ch), channel-major
__device__ float g_max[(size_t)BB * SS * 64]; // 4 MB : per-(b,s) max_k z3, [bs][o]
__device__ int   g_fps[BB * SS];
__device__ int   g_ball[BB * SS * KK];
__device__ float g_stats[3 * 128];          // per layer: [0..63]=sum, [64..127]=sumsq

// ---------------- packed f32x2 helpers (sm_103a) ---------------------------
__device__ __forceinline__ ull pack2(float lo, float hi) {
    ull r; asm("mov.b64 %0,{%1,%2};" : "=l"(r) : "f"(lo), "f"(hi)); return r;
}
__device__ __forceinline__ void unpack2(ull v, float& lo, float& hi) {
    asm("mov.b64 {%0,%1},%2;" : "=f"(lo), "=f"(hi) : "l"(v));
}
__device__ __forceinline__ ull add2(ull a, ull b) {
    ull r; asm("add.rn.f32x2 %0,%1,%2;" : "=l"(r) : "l"(a), "l"(b)); return r;
}
__device__ __forceinline__ ull mul2(ull a, ull b) {
    ull r; asm("mul.rn.f32x2 %0,%1,%2;" : "=l"(r) : "l"(a), "l"(b)); return r;
}
__device__ __forceinline__ ull fma2(ull a, ull b, ull c) {
    ull r; asm("fma.rn.f32x2 %0,%1,%2,%3;" : "=l"(r) : "l"(a), "l"(b), "l"(c)); return r;
}

// ============================================================================
// 1) Farthest point sampling. One block per batch, 512 threads x 16 points in
//    registers. Distance in the validated bit-exact (p-c)^2 packed form.
//    Per iteration: packed update + fmax tree, REDUX warp max, rescan
//    tie-break, REDUX min index -> per-warp 64-bit key. Block reduce is
//    ATOMIC-FREE: lane0 stores key to a double-buffered skey[2][16], one
//    barrier, then every warp redundantly shuffle-reduces the 16 keys
//    (identical max -> identical selection as the atomicMax version).
// ============================================================================
__global__ void __launch_bounds__(512) fps_kernel(const float* __restrict__ xyz)
{
    const int b = blockIdx.x;
    const float* base = xyz + (size_t)b * NN * 3;
    const int t = threadIdx.x;
    const int lane = t & 31, wid = t >> 5;

    // 16 points per thread: dd[j] <-> point index t + j*512
    ull px[8], py[8], pz[8];
    float dd[16];
#pragma unroll
    for (int k = 0; k < 8; k++) {
        const int p0 = t + (2 * k) * 512;
        const int p1 = t + (2 * k + 1) * 512;
        px[k] = pack2(base[3 * p0 + 0], base[3 * p1 + 0]);
        py[k] = pack2(base[3 * p0 + 1], base[3 * p1 + 1]);
        pz[k] = pack2(base[3 * p0 + 2], base[3 * p1 + 2]);
    }
#pragma unroll
    for (int j = 0; j < 16; j++) dd[j] = 1e10f;

    __shared__ ull skey[2][16];    // double-buffered per-warp keys (no reset needed)

    float cx = base[0], cy = base[1], cz = base[2];
    int cur = 0;

    for (int it = 0; it < SS; it++) {
        if (t == 0) g_fps[b * SS + it] = cur;

        const ull ncx = pack2(-cx, -cx);
        const ull ncy = pack2(-cy, -cy);
        const ull ncz = pack2(-cz, -cz);

        float m = 0.f;                     // dists >= 0, so 0 is a safe identity
#pragma unroll
        for (int k = 0; k < 8; k++) {
            ull dx = add2(px[k], ncx);
            ull dy = add2(py[k], ncy);
            ull dz = add2(pz[k], ncz);
            ull d2 = mul2(dx, dx);
            d2 = fma2(dy, dy, d2);
            d2 = fma2(dz, dz, d2);
            float dlo, dhi; unpack2(d2, dlo, dhi);
            const float nlo = fminf(dd[2 * k],     dlo);
            const float nhi = fminf(dd[2 * k + 1], dhi);
            dd[2 * k]     = nlo;
            dd[2 * k + 1] = nhi;
            m = fmaxf(m, fmaxf(nlo, nhi));
        }
        // warp max on float bits (all values >= 0 -> unsigned order == float order)
        const unsigned mb   = __float_as_uint(m);
        const unsigned wmax = __reduce_max_sync(0xffffffffu, mb);
        unsigned bi = 0xffffffffu;
        if (mb == wmax) {                  // usually 1 lane per warp
#pragma unroll
            for (int j = 15; j >= 0; j--)
                if (__float_as_uint(dd[j]) == wmax) bi = (unsigned)(t + j * 512);
        }
        const unsigned rid = __reduce_min_sync(0xffffffffu, bi);
        if (lane == 0)
            skey[it & 1][wid] = ((ull)wmax << 32)
                              | (ull)(unsigned)(NN - 1 - (int)rid);
        __syncthreads();

        // every warp redundantly reduces the 16 per-warp keys
        ull k = (lane < 16) ? skey[it & 1][lane] : 0ull;
#pragma unroll
        for (int off = 8; off > 0; off >>= 1) {
            ull o = __shfl_down_sync(0xffffffffu, k, off);
            if (o > k) k = o;
        }
        k = __shfl_sync(0xffffffffu, k, 0);

        cur = NN - 1 - (int)(unsigned)(k & 0xffffffffu);
        cx = base[3 * cur + 0];   // broadcast L1 hit
        cy = base[3 * cur + 1];
        cz = base[3 * cur + 2];
    }
}

// ============================================================================
// 2) new_xyz gather + ball query, smem-tiled. Block = 8 warps = 8 centroids,
//    all in the same batch. Block 0 also zeroes g_stats (all 384, strided).
// ============================================================================
#define TPTS 1024
__global__ void __launch_bounds__(256) bq_kernel(const float* __restrict__ xyz,
                                                 float* __restrict__ newxyz)
{
    const int tid = threadIdx.x;
    if (blockIdx.x == 0) {
        for (int i = tid; i < 384; i += 256) g_stats[i] = 0.f;
    }

    const int warp = tid >> 5, lane = tid & 31;
    const int gs = blockIdx.x * 8 + warp;          // 0 .. 16383
    const int b  = gs >> 11;                        // same for whole block
    const float* base = xyz + (size_t)b * NN * 3;

    __shared__ float spts[TPTS * 3];
    __shared__ int   sidx[8][KK];
    __shared__ int   sdone;
    if (tid == 0) sdone = 0;

    const int ci = g_fps[gs];
    const float cx = base[3 * ci + 0];
    const float cy = base[3 * ci + 1];
    const float cz = base[3 * ci + 2];
    if (lane < 3) newxyz[(size_t)gs * 3 + lane] = base[3 * ci + lane];

    const float r2 = (float)(0.2 * 0.2);
    int cnt = 0, first = 0x7fffffff;
    bool done = false;

    for (int tile = 0; tile < NN; tile += TPTS) {
        __syncthreads();
        if (sdone == 8) break;
        for (int i = tid; i < TPTS * 3; i += 256)
            spts[i] = base[(size_t)tile * 3 + i];
        __syncthreads();

        if (!done) {
            for (int p0 = 0; p0 < TPTS; p0 += 32) {
                const int p = p0 + lane;
                float dx = spts[3 * p + 0] - cx;
                float dy = spts[3 * p + 1] - cy;
                float dz = spts[3 * p + 2] - cz;
                float sq = dx * dx + dy * dy + dz * dz;
                bool  in = !(sq > r2);
                unsigned mm = __ballot_sync(0xffffffffu, in);
                if (in) {
                    int pos = cnt + __popc(mm & ((1u << lane) - 1u));
                    if (pos < KK) sidx[warp][pos] = tile + p;
                    if (pos == 0) first = tile + p;
                }
                cnt += __popc(mm);
                if (cnt >= KK) break;
            }
            if (cnt >= KK) {
                done = true;
                if (lane == 0) atomicAdd(&sdone, 1);
            }
        }
    }
#pragma unroll
    for (int off = 16; off > 0; off >>= 1)
        first = min(first, __shfl_down_sync(0xffffffffu, first, off));
    first = __shfl_sync(0xffffffffu, first, 0);

    const int cc = cnt < KK ? cnt : KK;
    const int v  = (lane < cc) ? sidx[warp][lane] : first;
    g_ball[(size_t)gs * KK + lane] = v;
}

// ============================================================================
// stats: warp reduce (sum, sumsq) then shared atomics
// ============================================================================
__device__ __forceinline__ void warp_stat_accum2(float v, float v2, int c, int lane,
                                                 float* ssum, float* ssq)
{
#pragma unroll
    for (int off = 16; off > 0; off >>= 1) {
        v  += __shfl_down_sync(0xffffffffu, v,  off);
        v2 += __shfl_down_sync(0xffffffffu, v2, off);
    }
    if (lane == 0) { atomicAdd(&ssum[c], v); atomicAdd(&ssq[c], v2); }
}

// BN affine from stats (same math as the old fin_kernel, computed inline)
__device__ __forceinline__ void bn_affine(int L, int c,
                                          const float* __restrict__ g,
                                          const float* __restrict__ be,
                                          float& a, float& cc)
{
    const float inv  = 1.f / (float)CNT;
    const float mean = g_stats[L * 128 + c] * inv;
    const float var  = g_stats[L * 128 + 64 + c] * inv - mean * mean;
    a  = g[c] * rsqrtf(var + 1e-5f);
    cc = be[c] - mean * a;
}

// ============================================================================
// 3) Layer 1: gather features (2 elements/thread), packed 6->32 conv, z1, stats.
// ============================================================================
__global__ void __launch_bounds__(256) l1_kernel(const float* __restrict__ xyz,
                                                 const float* __restrict__ pts,
                                                 const float* __restrict__ w,
                                                 const float* __restrict__ bias,
                                                 const float* __restrict__ newxyz)
{
    __shared__ ull   swd[192];
    __shared__ ull   sb2[32];
    __shared__ float ssum[32], ssq[32];
    const int tid = threadIdx.x, lane = tid & 31;
    if (tid < 192) { float v = w[tid]; swd[tid] = pack2(v, v); }
    if (tid < 32)  { float v = bias[tid]; sb2[tid] = pack2(v, v); ssum[tid] = 0.f; ssq[tid] = 0.f; }
    __syncthreads();

    const int gt = blockIdx.x * 256 + tid;        // pair id < CNT/2
    const int e0 = 2 * gt;
    const int bs = e0 >> 5;
    const int b  = bs >> 11;
    const int2 pp = *(const int2*)&g_ball[e0];
    const float* xb = xyz + (size_t)b * NN * 3;
    const float* pb = pts + (size_t)b * NN * 3;
    const float nx = newxyz[(size_t)bs * 3 + 0];
    const float ny = newxyz[(size_t)bs * 3 + 1];
    const float nz = newxyz[(size_t)bs * 3 + 2];

    ull in2[6];
    in2[0] = pack2(xb[3 * pp.x + 0] - nx, xb[3 * pp.y + 0] - nx);
    in2[1] = pack2(xb[3 * pp.x + 1] - ny, xb[3 * pp.y + 1] - ny);
    in2[2] = pack2(xb[3 * pp.x + 2] - nz, xb[3 * pp.y + 2] - nz);
    in2[3] = pack2(pb[3 * pp.x + 0], pb[3 * pp.y + 0]);
    in2[4] = pack2(pb[3 * pp.x + 1], pb[3 * pp.y + 1]);
    in2[5] = pack2(pb[3 * pp.x + 2], pb[3 * pp.y + 2]);

#pragma unroll 4
    for (int o = 0; o < 32; o++) {
        ull acc = sb2[o];
#pragma unroll
        for (int i = 0; i < 6; i++) acc = fma2(swd[o * 6 + i], in2[i], acc);
        *(ull*)&g_bufA[(size_t)o * CNT + e0] = acc;     // STG.64, coalesced
        float lo, hi; unpack2(acc, lo, hi);
        warp_stat_accum2(lo + hi, fmaf(hi, hi, lo * lo), o, lane, ssum, ssq);
    }
    __syncthreads();
    if (tid < 32) {
        atomicAdd(&g_stats[0 * 128 + tid],      ssum[tid]);
        atomicAdd(&g_stats[0 * 128 + 64 + tid], ssq[tid]);
    }
}

// ============================================================================
// 4) Layer 2: BN1+relu on z1 (affine computed inline from stats), packed
//    32->32 conv (2 elements/thread), z2, stats.
// ============================================================================
__global__ void __launch_bounds__(256) l2_kernel(const float* __restrict__ w,
                                                 const float* __restrict__ bias,
                                                 const float* __restrict__ g0,
                                                 const float* __restrict__ be0)
{
    __shared__ ull   swd[1024];
    __shared__ ull   sb2[32], sa2[32], sc2[32];
    __shared__ float ssum[32], ssq[32];
    const int tid = threadIdx.x, lane = tid & 31;
    for (int i = tid; i < 1024; i += 256) { float v = w[i]; swd[i] = pack2(v, v); }
    if (tid < 32) {
        float v = bias[tid]; sb2[tid] = pack2(v, v);
        float a, c; bn_affine(0, tid, g0, be0, a, c);
        sa2[tid] = pack2(a, a); sc2[tid] = pack2(c, c);
        ssum[tid] = 0.f; ssq[tid] = 0.f;
    }
    __syncthreads();

    const int e0 = 2 * (blockIdx.x * 256 + tid);
    ull h2[32];
#pragma unroll
    for (int i = 0; i < 32; i++) {
        ull z = *(const ull*)&g_bufA[(size_t)i * CNT + e0];
        ull t = fma2(sa2[i], z, sc2[i]);
        float lo, hi; unpack2(t, lo, hi);
        h2[i] = pack2(fmaxf(lo, 0.f), fmaxf(hi, 0.f));
    }
#pragma unroll 2
    for (int o = 0; o < 32; o++) {
        ull acc = sb2[o];
#pragma unroll
        for (int i = 0; i < 32; i++) acc = fma2(swd[o * 32 + i], h2[i], acc);
        *(ull*)&g_bufB[(size_t)o * CNT + e0] = acc;
        float lo, hi; unpack2(acc, lo, hi);
        warp_stat_accum2(lo + hi, fmaf(hi, hi, lo * lo), o, lane, ssum, ssq);
    }
    __syncthreads();
    if (tid < 32) {
        atomicAdd(&g_stats[1 * 128 + tid],      ssum[tid]);
        atomicAdd(&g_stats[1 * 128 + 64 + tid], ssq[tid]);
    }
}

// ============================================================================
// 5) Layer 3: BN2+relu on z2 (affine inline), packed 32->64 conv, stats, and
//    FUSED max over k: z3 never hits DRAM (bit-exact: a3>0, monotone fmaf/relu).
// ============================================================================
__global__ void __launch_bounds__(256) l3_kernel(const float* __restrict__ w,
                                                 const float* __restrict__ bias,
                                                 const float* __restrict__ g1,
                                                 const float* __restrict__ be1)
{
    __shared__ ull   swd[2048];       // 16KB
    __shared__ ull   sb2[64], sa2[32], sc2[32];
    __shared__ float ssum[64], ssq[64];
    __shared__ float smax[16][64];    // 16 bs-groups per block
    const int tid = threadIdx.x, lane = tid & 31, warp = tid >> 5;
    for (int i = tid; i < 2048; i += 256) { float v = w[i]; swd[i] = pack2(v, v); }
    if (tid < 64) { float v = bias[tid]; sb2[tid] = pack2(v, v); ssum[tid] = 0.f; ssq[tid] = 0.f; }
    if (tid < 32) {
        float a, c; bn_affine(1, tid, g1, be1, a, c);
        sa2[tid] = pack2(a, a); sc2[tid] = pack2(c, c);
    }
    __syncthreads();

    const int e0 = 2 * (blockIdx.x * 256 + tid);
    ull h2[32];
#pragma unroll
    for (int i = 0; i < 32; i++) {
        ull z = *(const ull*)&g_bufB[(size_t)i * CNT + e0];
        ull t = fma2(sa2[i], z, sc2[i]);
        float lo, hi; unpack2(t, lo, hi);
        h2[i] = pack2(fmaxf(lo, 0.f), fmaxf(hi, 0.f));
    }
    const int seg = (warp << 1) + (lane >> 4);    // bs-group within block (0..15)
#pragma unroll 1
    for (int o = 0; o < 64; o++) {
        ull acc = sb2[o];
#pragma unroll
        for (int i = 0; i < 32; i++) acc = fma2(swd[o * 32 + i], h2[i], acc);
        float lo, hi; unpack2(acc, lo, hi);
        float mx = fmaxf(lo, hi);
#pragma unroll
        for (int off = 8; off > 0; off >>= 1)
            mx = fmaxf(mx, __shfl_down_sync(0xffffffffu, mx, off, 16));
        if ((lane & 15) == 0) smax[seg][o] = mx;
        warp_stat_accum2(lo + hi, fmaf(hi, hi, lo * lo), o, lane, ssum, ssq);
    }
    __syncthreads();
    {
        const int bs0 = blockIdx.x * 16;
        for (int i = tid; i < 16 * 64; i += 256)
            g_max[(size_t)bs0 * 64 + i] = smax[i >> 6][i & 63];
    }
    if (tid < 64) {
        atomicAdd(&g_stats[2 * 128 + tid],      ssum[tid]);
        atomicAdd(&g_stats[2 * 128 + 64 + tid], ssq[tid]);
    }
}

// ============================================================================
// 6) Finalize: BN3 affine (inline from stats) + relu on the per-(bs,o) maxima.
// ============================================================================
__global__ void __launch_bounds__(256) final_kernel(const float* __restrict__ g2,
                                                    const float* __restrict__ be2,
                                                    float* __restrict__ out)
{
    __shared__ float sa[64], sc[64];
    const int tid = threadIdx.x;
    if (tid < 64) {
        float a, c; bn_affine(2, tid, g2, be2, a, c);
        sa[tid] = a; sc[tid] = c;
    }
    __syncthreads();

    const int idx = blockIdx.x * 256 + tid;       // < BB*SS*64
    const int o = idx & 63;
    const float v = g_max[idx];
    out[OUT_XYZ_ELEMS + idx] = fmaxf(fmaf(sa[o], v, sc[o]), 0.f);
}

// ============================================================================
extern "C" void kernel_launch(void* const* d_in, const int* in_sizes, int n_in,
                              void* d_out, int out_size)
{
    const float* xyz = (const float*)d_in[0];
    const float* pts = (const float*)d_in[1];
    const float* w0  = (const float*)d_in[2];
    const float* b0  = (const float*)d_in[3];
    const float* g0  = (const float*)d_in[4];
    const float* be0 = (const float*)d_in[5];
    const float* w1  = (const float*)d_in[6];
    const float* b1  = (const float*)d_in[7];
    const float* g1  = (const float*)d_in[8];
    const float* be1 = (const float*)d_in[9];
    const float* w2  = (const float*)d_in[10];
    const float* b2  = (const float*)d_in[11];
    const float* g2  = (const float*)d_in[12];
    const float* be2 = (const float*)d_in[13];
    float* out = (float*)d_out;

    fps_kernel<<<BB, 512>>>(xyz);
    bq_kernel<<<(BB * SS) / 8, 256>>>(xyz, out);
    l1_kernel<<<CNT / 512, 256>>>(xyz, pts, w0, b0, out);
    l2_kernel<<<CNT / 512, 256>>>(w1, b1, g0, be0);
    l3_kernel<<<CNT / 512, 256>>>(w2, b2, g1, be1);
    final_kernel<<<(BB * SS * 64) / 256, 256>>>(g2, be2, out);
}

// round 10
// speedup vs baseline: 1.9075x; 1.1974x over previous
#include <cuda_runtime.h>
#include <math.h>

#define BB 8
#define NN 8192
#define SS 2048
#define KK 32
#define CNT (BB*SS*KK)          // 524288 elements per layer
#define OUT_XYZ_ELEMS (BB*SS*3) // 49152

typedef unsigned long long ull;

// ---------------- scratch (static device memory; no runtime allocation) ----
__device__ float g_bufA[(size_t)CNT * 32];  // 64 MB : z1 (32ch), channel-major [c][e]
__device__ float g_bufB[(size_t)CNT * 32];  // 64 MB : z2 (32ch), channel-major
__device__ float g_max[(size_t)BB * SS * 64]; // 4 MB : per-(b,s) max_k z3, [bs][o]
__device__ int   g_fps[BB * SS];
__device__ int   g_ball[BB * SS * KK];
__device__ float g_stats[3 * 128];          // per layer: [0..63]=sum, [64..127]=sumsq

// ---------------- packed f32x2 helpers (sm_103a) ---------------------------
__device__ __forceinline__ ull pack2(float lo, float hi) {
    ull r; asm("mov.b64 %0,{%1,%2};" : "=l"(r) : "f"(lo), "f"(hi)); return r;
}
__device__ __forceinline__ void unpack2(ull v, float& lo, float& hi) {
    asm("mov.b64 {%0,%1},%2;" : "=f"(lo), "=f"(hi) : "l"(v));
}
__device__ __forceinline__ ull add2(ull a, ull b) {
    ull r; asm("add.rn.f32x2 %0,%1,%2;" : "=l"(r) : "l"(a), "l"(b)); return r;
}
__device__ __forceinline__ ull mul2(ull a, ull b) {
    ull r; asm("mul.rn.f32x2 %0,%1,%2;" : "=l"(r) : "l"(a), "l"(b)); return r;
}
__device__ __forceinline__ ull fma2(ull a, ull b, ull c) {
    ull r; asm("fma.rn.f32x2 %0,%1,%2,%3;" : "=l"(r) : "l"(a), "l"(b), "l"(c)); return r;
}

// ============================================================================
// 1) Farthest point sampling. One block per batch, 512 threads x 16 points in
//    registers. Inner loop: the validated bit-exact (p-c)^2 packed form with
//    scalar fmin/fmax (round-8 passing form). Tail restructured:
//      - lane0 stores warp max DIST BITS (32-bit) to sdist[wid]; bar1
//      - ONE REDUX over sdist[lane&15] -> block max bmax
//      - ONLY warps with wmax==bmax (warp-uniform) rescan for the smallest
//        local index, REDUX min, lane0 atomicMin into a 3-slot shared inbox
//      - bar2; everyone reads winner index, loads coords (L1 hit)
//    Selection is bit-identical: same max, same min-index tie-break.
// ============================================================================
__global__ void __launch_bounds__(512) fps_kernel(const float* __restrict__ xyz)
{
    const int b = blockIdx.x;
    const float* base = xyz + (size_t)b * NN * 3;
    const int t = threadIdx.x;
    const int lane = t & 31, wid = t >> 5;

    // 16 points per thread: dd[j] <-> point index t + j*512
    ull px[8], py[8], pz[8];
    float dd[16];
#pragma unroll
    for (int k = 0; k < 8; k++) {
        const int p0 = t + (2 * k) * 512;
        const int p1 = t + (2 * k + 1) * 512;
        px[k] = pack2(base[3 * p0 + 0], base[3 * p1 + 0]);
        py[k] = pack2(base[3 * p0 + 1], base[3 * p1 + 1]);
        pz[k] = pack2(base[3 * p0 + 2], base[3 * p1 + 2]);
    }
#pragma unroll
    for (int j = 0; j < 16; j++) dd[j] = 1e10f;

    __shared__ unsigned sdist[16];   // per-warp max dist bits (single-buffered,
                                     // protected by the bar1/bar2 sandwich)
    __shared__ unsigned sidxs[3];    // 3-slot rotating winner-index inbox
    if (t < 3) sidxs[t] = 0xffffffffu;
    __syncthreads();

    float cx = base[0], cy = base[1], cz = base[2];
    int cur = 0;
    int slot = 0, nslot = 1, rslot = 2;

    for (int it = 0; it < SS; it++) {
        if (t == 0) {
            g_fps[b * SS + it] = cur;
            sidxs[nslot] = 0xffffffffu;     // reset next slot (barrier-ordered)
        }
        const ull ncx = pack2(-cx, -cx);
        const ull ncy = pack2(-cy, -cy);
        const ull ncz = pack2(-cz, -cz);

        float m = 0.f;                      // dists >= 0, so 0 is a safe identity
#pragma unroll
        for (int k = 0; k < 8; k++) {
            ull dx = add2(px[k], ncx);
            ull dy = add2(py[k], ncy);
            ull dz = add2(pz[k], ncz);
            ull d2 = mul2(dx, dx);
            d2 = fma2(dy, dy, d2);
            d2 = fma2(dz, dz, d2);
            float dlo, dhi; unpack2(d2, dlo, dhi);
            const float nlo = fminf(dd[2 * k],     dlo);
            const float nhi = fminf(dd[2 * k + 1], dhi);
            dd[2 * k]     = nlo;
            dd[2 * k + 1] = nhi;
            m = fmaxf(m, fmaxf(nlo, nhi));
        }
        // warp max on float bits (all values >= 0 -> unsigned order == float order)
        const unsigned mb   = __float_as_uint(m);
        const unsigned wmax = __reduce_max_sync(0xffffffffu, mb);
        if (lane == 0) sdist[wid] = wmax;
        __syncthreads();                    // bar1

        // block max via ONE warp-REDUX over the 16 per-warp maxima
        const unsigned bmax = __reduce_max_sync(0xffffffffu, sdist[lane & 15]);

        if (wmax == bmax) {                 // warp-uniform: ~1 warp enters
            unsigned bi = 0xffffffffu;
            if (mb == bmax) {               // usually 1 lane
#pragma unroll
                for (int j = 15; j >= 0; j--)
                    if (__float_as_uint(dd[j]) == bmax) bi = (unsigned)(t + j * 512);
            }
            const unsigned rid = __reduce_min_sync(0xffffffffu, bi);
            if (lane == 0) atomicMin(&sidxs[slot], rid);
        }
        __syncthreads();                    // bar2

        cur = (int)sidxs[slot];
        cx = base[3 * cur + 0];   // broadcast L1 hit
        cy = base[3 * cur + 1];
        cz = base[3 * cur + 2];

        const int tmp = slot; slot = nslot; nslot = rslot; rslot = tmp;
    }
}

// ============================================================================
// 2) new_xyz gather + ball query, smem-tiled. Block = 8 warps = 8 centroids,
//    all in the same batch. Block 0 also zeroes g_stats (all 384, strided).
// ============================================================================
#define TPTS 1024
__global__ void __launch_bounds__(256) bq_kernel(const float* __restrict__ xyz,
                                                 float* __restrict__ newxyz)
{
    const int tid = threadIdx.x;
    if (blockIdx.x == 0) {
        for (int i = tid; i < 384; i += 256) g_stats[i] = 0.f;
    }

    const int warp = tid >> 5, lane = tid & 31;
    const int gs = blockIdx.x * 8 + warp;          // 0 .. 16383
    const int b  = gs >> 11;                        // same for whole block
    const float* base = xyz + (size_t)b * NN * 3;

    __shared__ float spts[TPTS * 3];
    __shared__ int   sidx[8][KK];
    __shared__ int   sdone;
    if (tid == 0) sdone = 0;

    const int ci = g_fps[gs];
    const float cx = base[3 * ci + 0];
    const float cy = base[3 * ci + 1];
    const float cz = base[3 * ci + 2];
    if (lane < 3) newxyz[(size_t)gs * 3 + lane] = base[3 * ci + lane];

    const float r2 = (float)(0.2 * 0.2);
    int cnt = 0, first = 0x7fffffff;
    bool done = false;

    for (int tile = 0; tile < NN; tile += TPTS) {
        __syncthreads();
        if (sdone == 8) break;
        for (int i = tid; i < TPTS * 3; i += 256)
            spts[i] = base[(size_t)tile * 3 + i];
        __syncthreads();

        if (!done) {
            for (int p0 = 0; p0 < TPTS; p0 += 32) {
                const int p = p0 + lane;
                float dx = spts[3 * p + 0] - cx;
                float dy = spts[3 * p + 1] - cy;
                float dz = spts[3 * p + 2] - cz;
                float sq = dx * dx + dy * dy + dz * dz;
                bool  in = !(sq > r2);
                unsigned mm = __ballot_sync(0xffffffffu, in);
                if (in) {
                    int pos = cnt + __popc(mm & ((1u << lane) - 1u));
                    if (pos < KK) sidx[warp][pos] = tile + p;
                    if (pos == 0) first = tile + p;
                }
                cnt += __popc(mm);
                if (cnt >= KK) break;
            }
            if (cnt >= KK) {
                done = true;
                if (lane == 0) atomicAdd(&sdone, 1);
            }
        }
    }
#pragma unroll
    for (int off = 16; off > 0; off >>= 1)
        first = min(first, __shfl_down_sync(0xffffffffu, first, off));
    first = __shfl_sync(0xffffffffu, first, 0);

    const int cc = cnt < KK ? cnt : KK;
    const int v  = (lane < cc) ? sidx[warp][lane] : first;
    g_ball[(size_t)gs * KK + lane] = v;
}

// ============================================================================
// stats: warp reduce (sum, sumsq) then shared atomics
// ============================================================================
__device__ __forceinline__ void warp_stat_accum2(float v, float v2, int c, int lane,
                                                 float* ssum, float* ssq)
{
#pragma unroll
    for (int off = 16; off > 0; off >>= 1) {
        v  += __shfl_down_sync(0xffffffffu, v,  off);
        v2 += __shfl_down_sync(0xffffffffu, v2, off);
    }
    if (lane == 0) { atomicAdd(&ssum[c], v); atomicAdd(&ssq[c], v2); }
}

// BN affine from stats (same math as the old fin_kernel, computed inline)
__device__ __forceinline__ void bn_affine(int L, int c,
                                          const float* __restrict__ g,
                                          const float* __restrict__ be,
                                          float& a, float& cc)
{
    const float inv  = 1.f / (float)CNT;
    const float mean = g_stats[L * 128 + c] * inv;
    const float var  = g_stats[L * 128 + 64 + c] * inv - mean * mean;
    a  = g[c] * rsqrtf(var + 1e-5f);
    cc = be[c] - mean * a;
}

// ============================================================================
// 3) Layer 1: gather features (2 elements/thread), packed 6->32 conv, z1, stats.
// ============================================================================
__global__ void __launch_bounds__(256) l1_kernel(const float* __restrict__ xyz,
                                                 const float* __restrict__ pts,
                                                 const float* __restrict__ w,
                                                 const float* __restrict__ bias,
                                                 const float* __restrict__ newxyz)
{
    __shared__ ull   swd[192];
    __shared__ ull   sb2[32];
    __shared__ float ssum[32], ssq[32];
    const int tid = threadIdx.x, lane = tid & 31;
    if (tid < 192) { float v = w[tid]; swd[tid] = pack2(v, v); }
    if (tid < 32)  { float v = bias[tid]; sb2[tid] = pack2(v, v); ssum[tid] = 0.f; ssq[tid] = 0.f; }
    __syncthreads();

    const int gt = blockIdx.x * 256 + tid;        // pair id < CNT/2
    const int e0 = 2 * gt;
    const int bs = e0 >> 5;
    const int b  = bs >> 11;
    const int2 pp = *(const int2*)&g_ball[e0];
    const float* xb = xyz + (size_t)b * NN * 3;
    const float* pb = pts + (size_t)b * NN * 3;
    const float nx = newxyz[(size_t)bs * 3 + 0];
    const float ny = newxyz[(size_t)bs * 3 + 1];
    const float nz = newxyz[(size_t)bs * 3 + 2];

    ull in2[6];
    in2[0] = pack2(xb[3 * pp.x + 0] - nx, xb[3 * pp.y + 0] - nx);
    in2[1] = pack2(xb[3 * pp.x + 1] - ny, xb[3 * pp.y + 1] - ny);
    in2[2] = pack2(xb[3 * pp.x + 2] - nz, xb[3 * pp.y + 2] - nz);
    in2[3] = pack2(pb[3 * pp.x + 0], pb[3 * pp.y + 0]);
    in2[4] = pack2(pb[3 * pp.x + 1], pb[3 * pp.y + 1]);
    in2[5] = pack2(pb[3 * pp.x + 2], pb[3 * pp.y + 2]);

#pragma unroll 4
    for (int o = 0; o < 32; o++) {
        ull acc = sb2[o];
#pragma unroll
        for (int i = 0; i < 6; i++) acc = fma2(swd[o * 6 + i], in2[i], acc);
        *(ull*)&g_bufA[(size_t)o * CNT + e0] = acc;     // STG.64, coalesced
        float lo, hi; unpack2(acc, lo, hi);
        warp_stat_accum2(lo + hi, fmaf(hi, hi, lo * lo), o, lane, ssum, ssq);
    }
    __syncthreads();
    if (tid < 32) {
        atomicAdd(&g_stats[0 * 128 + tid],      ssum[tid]);
        atomicAdd(&g_stats[0 * 128 + 64 + tid], ssq[tid]);
    }
}

// ============================================================================
// 4) Layer 2: BN1+relu on z1 (affine computed inline from stats), packed
//    32->32 conv (2 elements/thread), z2, stats.
// ============================================================================
__global__ void __launch_bounds__(256) l2_kernel(const float* __restrict__ w,
                                                 const float* __restrict__ bias,
                                                 const float* __restrict__ g0,
                                                 const float* __restrict__ be0)
{
    __shared__ ull   swd[1024];
    __shared__ ull   sb2[32], sa2[32], sc2[32];
    __shared__ float ssum[32], ssq[32];
    const int tid = threadIdx.x, lane = tid & 31;
    for (int i = tid; i < 1024; i += 256) { float v = w[i]; swd[i] = pack2(v, v); }
    if (tid < 32) {
        float v = bias[tid]; sb2[tid] = pack2(v, v);
        float a, c; bn_affine(0, tid, g0, be0, a, c);
        sa2[tid] = pack2(a, a); sc2[tid] = pack2(c, c);
        ssum[tid] = 0.f; ssq[tid] = 0.f;
    }
    __syncthreads();

    const int e0 = 2 * (blockIdx.x * 256 + tid);
    ull h2[32];
#pragma unroll
    for (int i = 0; i < 32; i++) {
        ull z = *(const ull*)&g_bufA[(size_t)i * CNT + e0];
        ull t = fma2(sa2[i], z, sc2[i]);
        float lo, hi; unpack2(t, lo, hi);
        h2[i] = pack2(fmaxf(lo, 0.f), fmaxf(hi, 0.f));
    }
#pragma unroll 2
    for (int o = 0; o < 32; o++) {
        ull acc = sb2[o];
#pragma unroll
        for (int i = 0; i < 32; i++) acc = fma2(swd[o * 32 + i], h2[i], acc);
        *(ull*)&g_bufB[(size_t)o * CNT + e0] = acc;
        float lo, hi; unpack2(acc, lo, hi);
        warp_stat_accum2(lo + hi, fmaf(hi, hi, lo * lo), o, lane, ssum, ssq);
    }
    __syncthreads();
    if (tid < 32) {
        atomicAdd(&g_stats[1 * 128 + tid],      ssum[tid]);
        atomicAdd(&g_stats[1 * 128 + 64 + tid], ssq[tid]);
    }
}

// ============================================================================
// 5) Layer 3: BN2+relu on z2 (affine inline), packed 32->64 conv, stats, and
//    FUSED max over k: z3 never hits DRAM (bit-exact: a3>0, monotone fmaf/relu).
// ============================================================================
__global__ void __launch_bounds__(256) l3_kernel(const float* __restrict__ w,
                                                 const float* __restrict__ bias,
                                                 const float* __restrict__ g1,
                                                 const float* __restrict__ be1)
{
    __shared__ ull   swd[2048];       // 16KB
    __shared__ ull   sb2[64], sa2[32], sc2[32];
    __shared__ float ssum[64], ssq[64];
    __shared__ float smax[16][64];    // 16 bs-groups per block
    const int tid = threadIdx.x, lane = tid & 31, warp = tid >> 5;
    for (int i = tid; i < 2048; i += 256) { float v = w[i]; swd[i] = pack2(v, v); }
    if (tid < 64) { float v = bias[tid]; sb2[tid] = pack2(v, v); ssum[tid] = 0.f; ssq[tid] = 0.f; }
    if (tid < 32) {
        float a, c; bn_affine(1, tid, g1, be1, a, c);
        sa2[tid] = pack2(a, a); sc2[tid] = pack2(c, c);
    }
    __syncthreads();

    const int e0 = 2 * (blockIdx.x * 256 + tid);
    ull h2[32];
#pragma unroll
    for (int i = 0; i < 32; i++) {
        ull z = *(const ull*)&g_bufB[(size_t)i * CNT + e0];
        ull t = fma2(sa2[i], z, sc2[i]);
        float lo, hi; unpack2(t, lo, hi);
        h2[i] = pack2(fmaxf(lo, 0.f), fmaxf(hi, 0.f));
    }
    const int seg = (warp << 1) + (lane >> 4);    // bs-group within block (0..15)
#pragma unroll 1
    for (int o = 0; o < 64; o++) {
        ull acc = sb2[o];
#pragma unroll
        for (int i = 0; i < 32; i++) acc = fma2(swd[o * 32 + i], h2[i], acc);
        float lo, hi; unpack2(acc, lo, hi);
        float mx = fmaxf(lo, hi);
#pragma unroll
        for (int off = 8; off > 0; off >>= 1)
            mx = fmaxf(mx, __shfl_down_sync(0xffffffffu, mx, off, 16));
        if ((lane & 15) == 0) smax[seg][o] = mx;
        warp_stat_accum2(lo + hi, fmaf(hi, hi, lo * lo), o, lane, ssum, ssq);
    }
    __syncthreads();
    {
        const int bs0 = blockIdx.x * 16;
        for (int i = tid; i < 16 * 64; i += 256)
            g_max[(size_t)bs0 * 64 + i] = smax[i >> 6][i & 63];
    }
    if (tid < 64) {
        atomicAdd(&g_stats[2 * 128 + tid],      ssum[tid]);
        atomicAdd(&g_stats[2 * 128 + 64 + tid], ssq[tid]);
    }
}

// ============================================================================
// 6) Finalize: BN3 affine (inline from stats) + relu on the per-(bs,o) maxima.
// ============================================================================
__global__ void __launch_bounds__(256) final_kernel(const float* __restrict__ g2,
                                                    const float* __restrict__ be2,
                                                    float* __restrict__ out)
{
    __shared__ float sa[64], sc[64];
    const int tid = threadIdx.x;
    if (tid < 64) {
        float a, c; bn_affine(2, tid, g2, be2, a, c);
        sa[tid] = a; sc[tid] = c;
    }
    __syncthreads();

    const int idx = blockIdx.x * 256 + tid;       // < BB*SS*64
    const int o = idx & 63;
    const float v = g_max[idx];
    out[OUT_XYZ_ELEMS + idx] = fmaxf(fmaf(sa[o], v, sc[o]), 0.f);
}

// ============================================================================
extern "C" void kernel_launch(void* const* d_in, const int* in_sizes, int n_in,
                              void* d_out, int out_size)
{
    const float* xyz = (const float*)d_in[0];
    const float* pts = (const float*)d_in[1];
    const float* w0  = (const float*)d_in[2];
    const float* b0  = (const float*)d_in[3];
    const float* g0  = (const float*)d_in[4];
    const float* be0 = (const float*)d_in[5];
    const float* w1  = (const float*)d_in[6];
    const float* b1  = (const float*)d_in[7];
    const float* g1  = (const float*)d_in[8];
    const float* be1 = (const float*)d_in[9];
    const float* w2  = (const float*)d_in[10];
    const float* b2  = (const float*)d_in[11];
    const float* g2  = (const float*)d_in[12];
    const float* be2 = (const float*)d_in[13];
    float* out = (float*)d_out;

    fps_kernel<<<BB, 512>>>(xyz);
    bq_kernel<<<(BB * SS) / 8, 256>>>(xyz, out);
    l1_kernel<<<CNT / 512, 256>>>(xyz, pts, w0, b0, out);
    l2_kernel<<<CNT / 512, 256>>>(w1, b1, g0, be0);
    l3_kernel<<<CNT / 512, 256>>>(w2, b2, g1, be1);
    final_kernel<<<(BB * SS * 64) / 256, 256>>>(g2, be2, out);
}